// round 7
// baseline (speedup 1.0000x reference)
#include <cuda_runtime.h>
#include <cuda_bf16.h>
#include <cstdint>

// LightGCN bipartite message passing:
//   agg_items[i] += norm_e * user_emb[u_e]   for each edge e=(u,i)
//   agg_users[u] += norm_e * item_emb[i_e]
// Output buffer = [agg_users (100000x64) | agg_items (50000x64)], f32.
//
// Inputs (metadata order): user_emb f32[100000*64], item_emb f32[50000*64],
//                          edge_norm f32[4000000], u_idx i32[4M], i_idx i32[4M]

#define NUM_USERS 100000
#define NUM_ITEMS 50000
#define DIM 64
#define CHUNKS (DIM / 4)   // 16 float4 chunks per row

// 16B vector reduction to global memory (sm_90+): one RED, no return path.
__device__ __forceinline__ void red_add_f32x4(float4* addr, float4 v)
{
    asm volatile("red.global.add.v4.f32 [%0], {%1, %2, %3, %4};"
                 :: "l"(addr), "f"(v.x), "f"(v.y), "f"(v.z), "f"(v.w)
                 : "memory");
}

__global__ void __launch_bounds__(256)
lightgcn_edge_kernel(const float4* __restrict__ user_emb,
                     const float4* __restrict__ item_emb,
                     const float*  __restrict__ edge_norm,
                     const int*    __restrict__ u_idx,
                     const int*    __restrict__ i_idx,
                     float4* __restrict__ agg_users,
                     float4* __restrict__ agg_items,
                     int num_edges)
{
    unsigned t = blockIdx.x * blockDim.x + threadIdx.x;
    int edge  = (int)(t >> 4);      // 16 threads per edge
    int chunk = (int)(t & 15);
    if (edge >= num_edges) return;

    int   u = __ldg(&u_idx[edge]);
    int   i = __ldg(&i_idx[edge]);
    float n = __ldg(&edge_norm[edge]);

    float4 ue = __ldg(&user_emb[u * CHUNKS + chunk]);
    float4 ie = __ldg(&item_emb[i * CHUNKS + chunk]);

    float4 msg_item = make_float4(n * ue.x, n * ue.y, n * ue.z, n * ue.w);
    float4 msg_user = make_float4(n * ie.x, n * ie.y, n * ie.z, n * ie.w);

    red_add_f32x4(&agg_items[i * CHUNKS + chunk], msg_item);
    red_add_f32x4(&agg_users[u * CHUNKS + chunk], msg_user);
}

extern "C" void kernel_launch(void* const* d_in, const int* in_sizes, int n_in,
                              void* d_out, int out_size)
{
    const float4* user_emb  = (const float4*)d_in[0];
    const float4* item_emb  = (const float4*)d_in[1];
    const float*  edge_norm = (const float*)d_in[2];
    const int*    u_idx     = (const int*)d_in[3];
    const int*    i_idx     = (const int*)d_in[4];

    int num_edges = in_sizes[2];  // 4,000,000

    float4* agg_users = (float4*)d_out;
    float4* agg_items = agg_users + (size_t)NUM_USERS * CHUNKS;

    // Output is poisoned with 0xAA — zero it (graph-capturable memset node).
    cudaMemsetAsync(d_out, 0, (size_t)out_size * sizeof(float), 0);

    const int threads = 256;
    long long total = (long long)num_edges * 16;
    int blocks = (int)((total + threads - 1) / threads);
    lightgcn_edge_kernel<<<blocks, threads>>>(user_emb, item_emb, edge_norm,
                                              u_idx, i_idx,
                                              agg_users, agg_items, num_edges);
}

// round 10
// speedup vs baseline: 1.3082x; 1.3082x over previous
#include <cuda_runtime.h>
#include <cuda_bf16.h>
#include <cstdint>

// LightGCN bipartite message passing, grouped-scatter formulation.
//   agg_items[i] = sum_{e: i_idx[e]==i} norm_e * user_emb[u_idx[e]]
//   agg_users[u] = sum_{e: u_idx[e]==u} norm_e * item_emb[i_idx[e]]
// Output = [agg_users (100000x64) | agg_items (50000x64)], f32.
//
// Pipeline (one stream, graph-capturable, 5 kernel launches):
//   1. zero_counts             — reset per-bin cursors + overflow counter
//   2. scatter_kernel          — bin every edge's {src, norm} into its
//                                destination's fixed-capacity payload row
//   3. agg (items)             — one warp per item: register-accumulate, 1 store
//   4. agg (users)             — one warp per user: register-accumulate, 1 store
//   5. cleanup_kernel          — RED any capacity-overflow edges (normally 0)

#define NUM_USERS 100000
#define NUM_ITEMS 50000
#define DIM       64
#define CAP_I     176      // Poisson(80): P(overflow) ~ e^-43 per bin
#define CAP_U     112      // Poisson(40): P(overflow) ~ e^-43 per bin
#define OVF_CAP   16384

// Scratch: static __device__ arrays (no allocation anywhere).
__device__ int2 d_item_pay[(size_t)NUM_ITEMS * CAP_I];   // {u, norm_bits}
__device__ int2 d_user_pay[(size_t)NUM_USERS * CAP_U];   // {i, norm_bits}
__device__ int  d_item_cnt[NUM_ITEMS];
__device__ int  d_user_cnt[NUM_USERS];
__device__ int4 d_ovf[OVF_CAP];                          // {dest, src, norm_bits, side}
__device__ int  d_ovf_cnt;

__device__ __forceinline__ void red_add_f32x4(float4* addr, float4 v)
{
    asm volatile("red.global.add.v4.f32 [%0], {%1, %2, %3, %4};"
                 :: "l"(addr), "f"(v.x), "f"(v.y), "f"(v.z), "f"(v.w)
                 : "memory");
}

__global__ void zero_counts()
{
    int t = blockIdx.x * blockDim.x + threadIdx.x;
    if (t < NUM_ITEMS) d_item_cnt[t] = 0;
    if (t < NUM_USERS) d_user_cnt[t] = 0;
    if (t == 0) d_ovf_cnt = 0;
}

__global__ void __launch_bounds__(256)
scatter_kernel(const int*   __restrict__ u_idx,
               const int*   __restrict__ i_idx,
               const float* __restrict__ edge_norm,
               int num_edges)
{
    int e = blockIdx.x * blockDim.x + threadIdx.x;
    if (e >= num_edges) return;

    int u  = __ldg(&u_idx[e]);
    int i  = __ldg(&i_idx[e]);
    int nb = __float_as_int(__ldg(&edge_norm[e]));

    int si = atomicAdd(&d_item_cnt[i], 1);
    if (si < CAP_I) {
        d_item_pay[i * CAP_I + si] = make_int2(u, nb);
    } else {
        int s = atomicAdd(&d_ovf_cnt, 1);
        if (s < OVF_CAP) d_ovf[s] = make_int4(i, u, nb, 0);   // side 0: item dest
    }

    int su = atomicAdd(&d_user_cnt[u], 1);
    if (su < CAP_U) {
        d_user_pay[u * CAP_U + su] = make_int2(i, nb);
    } else {
        int s = atomicAdd(&d_ovf_cnt, 1);
        if (s < OVF_CAP) d_ovf[s] = make_int4(u, i, nb, 1);   // side 1: user dest
    }
}

// One warp per segment. Each lane owns 2 consecutive dims (float2).
// Payload load is lane-uniform (L1 broadcast); embedding gather is a
// coalesced 256B row read (L2-resident); accumulate in registers; one store.
__device__ __forceinline__ void agg_segment(const float2* __restrict__ emb,
                                            const int2*   __restrict__ pay,
                                            const int*    __restrict__ cnts,
                                            float2*       __restrict__ out,
                                            int num_seg, int cap)
{
    int warp = (blockIdx.x * blockDim.x + threadIdx.x) >> 5;
    int lane = threadIdx.x & 31;
    if (warp >= num_seg) return;

    int cnt = min(cnts[warp], cap);
    long base = (long)warp * cap;

    float2 acc = make_float2(0.f, 0.f);
    int2 p = (cnt > 0) ? __ldg(&pay[base]) : make_int2(0, 0);

    for (int e = 0; e < cnt; e++) {
        int2 pn = (e + 1 < cnt) ? __ldg(&pay[base + e + 1]) : p;  // prefetch next
        float  n = __int_as_float(p.y);
        float2 v = __ldg(&emb[(long)p.x * (DIM / 2) + lane]);
        acc.x = fmaf(n, v.x, acc.x);
        acc.y = fmaf(n, v.y, acc.y);
        p = pn;
    }
    out[(long)warp * (DIM / 2) + lane] = acc;   // plain store covers 0xAA poison
}

__global__ void __launch_bounds__(256)
agg_items_kernel(const float2* __restrict__ user_emb, float2* __restrict__ agg_items)
{
    agg_segment(user_emb, d_item_pay, d_item_cnt, agg_items, NUM_ITEMS, CAP_I);
}

__global__ void __launch_bounds__(256)
agg_users_kernel(const float2* __restrict__ item_emb, float2* __restrict__ agg_users)
{
    agg_segment(item_emb, d_user_pay, d_user_cnt, agg_users, NUM_USERS, CAP_U);
}

// Handles capacity-overflow edges (normally zero). 16 threads per entry,
// float4 RED into the already-written output rows.
__global__ void cleanup_kernel(const float4* __restrict__ user_emb,
                               const float4* __restrict__ item_emb,
                               float4* __restrict__ agg_users,
                               float4* __restrict__ agg_items)
{
    int n = d_ovf_cnt;
    if (n > OVF_CAP) n = OVF_CAP;
    int total = n * 16;
    int stride = gridDim.x * blockDim.x;
    for (int t = blockIdx.x * blockDim.x + threadIdx.x; t < total; t += stride) {
        int entry = t >> 4, chunk = t & 15;
        int4 o = d_ovf[entry];
        float nn = __int_as_float(o.z);
        const float4* src = (o.w == 0) ? user_emb : item_emb;
        float4*       dst = (o.w == 0) ? agg_items : agg_users;
        float4 v = __ldg(&src[(long)o.y * 16 + chunk]);
        float4 m = make_float4(nn * v.x, nn * v.y, nn * v.z, nn * v.w);
        red_add_f32x4(&dst[(long)o.x * 16 + chunk], m);
    }
}

extern "C" void kernel_launch(void* const* d_in, const int* in_sizes, int n_in,
                              void* d_out, int out_size)
{
    const float* user_emb  = (const float*)d_in[0];
    const float* item_emb  = (const float*)d_in[1];
    const float* edge_norm = (const float*)d_in[2];
    const int*   u_idx     = (const int*)d_in[3];
    const int*   i_idx     = (const int*)d_in[4];

    int num_edges = in_sizes[2];   // 4,000,000

    float* agg_users = (float*)d_out;
    float* agg_items = agg_users + (size_t)NUM_USERS * DIM;

    zero_counts<<<(NUM_USERS + 255) / 256, 256>>>();

    scatter_kernel<<<(num_edges + 255) / 256, 256>>>(u_idx, i_idx, edge_norm, num_edges);

    // one warp per segment: 8 warps per 256-thread block
    agg_items_kernel<<<(NUM_ITEMS * 32 + 255) / 256, 256>>>(
        (const float2*)user_emb, (float2*)agg_items);
    agg_users_kernel<<<(NUM_USERS * 32 + 255) / 256, 256>>>(
        (const float2*)item_emb, (float2*)agg_users);

    cleanup_kernel<<<32, 256>>>((const float4*)user_emb, (const float4*)item_emb,
                                (float4*)agg_users, (float4*)agg_items);
}